// round 14
// baseline (speedup 1.0000x reference)
#include <cuda_runtime.h>
#include <cstdint>

typedef unsigned long long u64;

// ---------------------------------------------------------------------------
// f32x2 packed helpers (Blackwell sm_103a)
// ---------------------------------------------------------------------------
__device__ __forceinline__ u64 pack2(float a, float b) {
    u64 r;
    asm("mov.b64 %0, {%1,%2};" : "=l"(r) : "f"(a), "f"(b));
    return r;
}
__device__ __forceinline__ u64 dup2(float a) { return pack2(a, a); }
__device__ __forceinline__ u64 ffma2(u64 a, u64 b, u64 c) {
    u64 d;
    asm("fma.rn.f32x2 %0, %1, %2, %3;" : "=l"(d) : "l"(a), "l"(b), "l"(c));
    return d;
}
__device__ __forceinline__ u64 fmul2(u64 a, u64 b) {
    u64 d;
    asm("mul.rn.f32x2 %0, %1, %2;" : "=l"(d) : "l"(a), "l"(b));
    return d;
}
__device__ __forceinline__ void unpack2(u64 v, float& lo, float& hi) {
    asm("mov.b64 {%0,%1}, %2;" : "=f"(lo), "=f"(hi) : "l"(v));
}

// ---------------------------------------------------------------------------
// Coefficient table: index p*9+q (p = t0*3+t1, q = t2*3+t3); each entry is
// a float4 over the 4 outputs (two packed f32x2 halves).
// Setup kernel writes g_coef (global); host-side cudaMemcpyToSymbolAsync
// moves it into c_coef (the ONLY ordering that makes constant-bank updates
// visible to LDC — device-side stores to the bank are ignored by the
// immutable constant cache, R10/R11 evidence).
// ---------------------------------------------------------------------------
__device__ __align__(16) float g_coef[324];
__constant__ __align__(16) ulonglong2 c_coef[81];

__device__ __forceinline__ float2 cmulf(float2 a, float2 b) {
    return make_float2(a.x * b.x - a.y * b.y, a.x * b.y + a.y * b.x);
}
__device__ __forceinline__ float2 caddf(float2 a, float2 b) {
    return make_float2(a.x + b.x, a.y + b.y);
}

// ---------------------------------------------------------------------------
// Setup kernel (1 block, 384 threads), fully parallel.
// ---------------------------------------------------------------------------
__global__ void build_coef_kernel(
    const float* w0, const float* w1, const float* w2, const float* w3,
    const float* w4, const float* w5, const float* w6, const float* w7,
    const float* w8, const float* w9, const float* w10, const float* w11,
    const float* w12, const float* w13) {
    __shared__ float2 gm[14][4];        // 2x2 gate matrices
    __shared__ float2 su4m[2][16];      // two 4x4 SU4 matrices, row-major
    __shared__ float2 Ubuf[2][16][16];  // [buf][row k][col c]
    __shared__ float2 Ut[16][18];       // transposed Ut[c][k]; 144B rows keep
                                        // 16B alignment for LDS.128
    __shared__ float Gsh[4][16][16];    // G[i][r][c]
    const float* W[14] = {w0, w1, w2, w3, w4, w5, w6, w7, w8, w9, w10, w11, w12, w13};

    int tid = threadIdx.x;

    // ---- Stage 1: gate matrices ------------------------------------------
    if (tid < 14) {
        int j = tid % 7;
        const float* w = W[tid];
        float2 m00, m01, m10, m11;
        if (j == 0 || j == 1 || j == 5 || j == 6) {  // U3
            float th = w[0], ph = w[1], lm = w[2];
            float st, ct, sph, cph, sl, cl;
            __sincosf(0.5f * th, &st, &ct);
            __sincosf(ph, &sph, &cph);
            __sincosf(lm, &sl, &cl);
            m00 = make_float2(ct, 0.f);
            m01 = make_float2(-cl * st, -sl * st);
            m10 = make_float2(cph * st, sph * st);
            float cpl = cph * cl - sph * sl;
            float spl = sph * cl + cph * sl;
            m11 = make_float2(cpl * ct, spl * ct);
        } else if (j == 2 || j == 4) {  // RY
            float s, c;
            __sincosf(0.5f * w[0], &s, &c);
            m00 = make_float2(c, 0.f); m01 = make_float2(-s, 0.f);
            m10 = make_float2(s, 0.f); m11 = make_float2(c, 0.f);
        } else {  // RZ
            float s, c;
            __sincosf(0.5f * w[0], &s, &c);
            m00 = make_float2(c, -s); m01 = make_float2(0.f, 0.f);
            m10 = make_float2(0.f, 0.f); m11 = make_float2(c, s);
        }
        gm[tid][0] = m00; gm[tid][1] = m01; gm[tid][2] = m10; gm[tid][3] = m11;
    }
    __syncthreads();

    // ---- Stage 2: two 4x4 SU4 matrices (a = high bit, b = low bit) -------
    if (tid < 8) {
        int L = tid >> 2, c = tid & 3;
        float2 v[4];
#pragma unroll
        for (int i = 0; i < 4; i++) v[i] = make_float2(i == c ? 1.f : 0.f, 0.f);

        auto ap = [&](int gi, int m) {
            float2 g00 = gm[L * 7 + gi][0], g01 = gm[L * 7 + gi][1];
            float2 g10 = gm[L * 7 + gi][2], g11 = gm[L * 7 + gi][3];
#pragma unroll
            for (int idx = 0; idx < 4; idx++) {
                if (!(idx & m)) {
                    float2 lo = v[idx], hi = v[idx | m];
                    v[idx]     = caddf(cmulf(g00, lo), cmulf(g01, hi));
                    v[idx | m] = caddf(cmulf(g10, lo), cmulf(g11, hi));
                }
            }
        };
        auto swp = [&](int i, int j) { float2 t = v[i]; v[i] = v[j]; v[j] = t; };

        ap(0, 2);   // U3 a
        ap(1, 1);   // U3 b
        swp(2, 3);  // CNOT a->b
        ap(2, 2);   // RY a
        ap(3, 1);   // RZ b
        swp(1, 3);  // CNOT b->a
        ap(4, 2);   // RY a
        swp(2, 3);  // CNOT a->b
        ap(5, 2);   // U3 a
        ap(6, 1);   // U3 b
#pragma unroll
        for (int r = 0; r < 4; r++) su4m[L][r * 4 + c] = v[r];
    }

    // ---- Stage 3: build 16x16 unitary -----------------------------------
    if (tid < 256) {
        int k = tid >> 4, c = tid & 15;
        Ubuf[0][k][c] = make_float2(k == c ? 1.f : 0.f, 0.f);
    }

    const int gL[8]  = {0, 0, 0, 0, 1, 1, 1, 1};
    const int gwa[8] = {0, 1, 2, 3, 0, 1, 2, 3};
    const int gwb[8] = {1, 2, 3, 0, 1, 2, 3, 0};
    int cur = 0;
#pragma unroll
    for (int g = 0; g < 8; g++) {
        __syncthreads();
        if (tid < 256) {
            int k = tid >> 4, c = tid & 15;
            int ma = 1 << (3 - gwa[g]);
            int mb = 1 << (3 - gwb[g]);
            int i2 = ((k & ma) ? 2 : 0) | ((k & mb) ? 1 : 0);
            int base = k & ~(ma | mb);
            int L = gL[g];
            float2 acc = make_float2(0.f, 0.f);
#pragma unroll
            for (int j = 0; j < 4; j++) {
                int row = base | ((j & 2) ? ma : 0) | ((j & 1) ? mb : 0);
                acc = caddf(acc, cmulf(su4m[L][i2 * 4 + j], Ubuf[cur][row][c]));
            }
            Ubuf[cur ^ 1][k][c] = acc;
        }
        cur ^= 1;
    }
    __syncthreads();

    // ---- Stage 3.5: transpose so column access is contiguous over k -----
    if (tid < 256) {
        int k = tid >> 4, c = tid & 15;
        Ut[c][k] = Ubuf[cur][k][c];
    }
    __syncthreads();

    // ---- Stage 4a: G[i][r][c] = sum_k s_i(k) Re(conj U[k][r] U[k][c]) ---
    if (tid < 256) {
        int r = tid >> 4, c = tid & 15;
        float g[4] = {0.f, 0.f, 0.f, 0.f};
        const float4* pr = reinterpret_cast<const float4*>(&Ut[r][0]);
        const float4* pc = reinterpret_cast<const float4*>(&Ut[c][0]);
#pragma unroll
        for (int j = 0; j < 8; j++) {
            float4 ar = pr[j], ac = pc[j];
            float d0 = ar.x * ac.x + ar.y * ac.y;  // k = 2j
            float d1 = ar.z * ac.z + ar.w * ac.w;  // k = 2j+1
            int k0 = 2 * j, k1 = 2 * j + 1;
#pragma unroll
            for (int i = 0; i < 4; i++) {
                float s0 = ((k0 >> (3 - i)) & 1) ? -d0 : d0;
                float s1 = ((k1 >> (3 - i)) & 1) ? -d1 : d1;
                g[i] += s0 + s1;
            }
        }
#pragma unroll
        for (int i = 0; i < 4; i++) Gsh[i][r][c] = g[i];
    }
    __syncthreads();

    // ---- Stage 4b: coefficients -> global table --------------------------
    if (tid < 324) {
        int i = tid & 3;
        int pq = tid >> 2;  // 0..80
        int q = pq % 9, p = pq / 9;
        int t[4] = {p / 3, p % 3, q / 3, q % 3};
        int mask = 0, zmask = 0;
#pragma unroll
        for (int w = 0; w < 4; w++) {
            if (t[w] == 2) mask |= 1 << (3 - w);
            if (t[w] == 1) zmask |= 1 << (3 - w);
        }
        float acc = 0.f;
#pragma unroll
        for (int r = 0; r < 16; r++) {
            float sgn = (__popc(r & zmask) & 1) ? -1.f : 1.f;
            acc += sgn * Gsh[i][r][r ^ mask];
        }
        g_coef[(p * 9 + q) * 4 + i] = acc * 0.0625f;
    }
}

// ---------------------------------------------------------------------------
// Main kernel: 4 patches per thread, 128 threads/block.  Every coefficient
// LDC.128 (constant port, compile-time offset) feeds 8 ffma2 -> constant-port
// time (~9K cyc/SMSP) drops well below the fma-pipe floor (~19K): FMA is the
// sole bind.  One warp with 8 independent accumulator chains saturates the
// fma pipe (rt_SMSP=2), so low occupancy from ~130 regs is fine.
// ---------------------------------------------------------------------------
struct PatchW {
    u64 qwd[9];    // duplicated (w2 x w3) pair products, index 1..8 used
    float pws[9];  // (w0 x w1) pair products, index 1..8 used
};

__device__ __forceinline__ void make_weights(float4 xv, PatchW& P) {
    float xs[4] = {xv.x, xv.y, xv.z, xv.w};
    float us[4];
#pragma unroll
    for (int w = 0; w < 4; w++) {
        float e = __expf(-xs[w]);
        us[w] = __fdividef(1.0f, 1.0f + e) - 0.5f;  // u in (-0.5, 0.5)
    }
    // packed polynomials: lanes = (wire0,wire1) and (wire2,wire3)
    u64 u01 = pack2(us[0], us[1]);
    u64 u23 = pack2(us[2], us[3]);
    float cw[4], sw[4];
#pragma unroll
    for (int h = 0; h < 2; h++) {
        u64 uu = h ? u23 : u01;
        u64 z = fmul2(uu, uu);
        // sin(pi*u) deg-9 / cos(pi*u) deg-8 (abs err < 3e-5 on [-0.5,0.5])
        u64 sp = ffma2(z, dup2(0.0821458866111282f), dup2(-0.599264529320792f));
        sp = ffma2(z, sp, dup2(2.55016403987735f));
        sp = ffma2(z, sp, dup2(-5.16771278004997f));
        sp = ffma2(z, sp, dup2(3.14159265358979f));
        sp = fmul2(sp, uu);
        u64 cp = ffma2(z, dup2(0.235330630358514f), dup2(-1.33526276885459f));
        cp = ffma2(z, cp, dup2(4.05871212641677f));
        cp = ffma2(z, cp, dup2(-4.93480220054468f));
        cp = ffma2(z, cp, dup2(1.0f));
        float a, b;
        unpack2(sp, a, b);
        cw[2 * h] = -a; cw[2 * h + 1] = -b;  // cos a = -sin(pi*u)
        unpack2(cp, a, b);
        sw[2 * h] = a; sw[2 * h + 1] = b;    // sin a =  cos(pi*u)
    }
    P.qwd[1] = dup2(cw[3]);
    P.qwd[2] = dup2(sw[3]);
    P.qwd[3] = dup2(cw[2]);
    P.qwd[4] = dup2(cw[2] * cw[3]);
    P.qwd[5] = dup2(cw[2] * sw[3]);
    P.qwd[6] = dup2(sw[2]);
    P.qwd[7] = dup2(sw[2] * cw[3]);
    P.qwd[8] = dup2(sw[2] * sw[3]);
    P.pws[1] = cw[1];
    P.pws[2] = sw[1];
    P.pws[3] = cw[0];
    P.pws[4] = cw[0] * cw[1];
    P.pws[5] = cw[0] * sw[1];
    P.pws[6] = sw[0];
    P.pws[7] = sw[0] * cw[1];
    P.pws[8] = sw[0] * sw[1];
}

__global__ void __launch_bounds__(128) quanv_main(const float4* __restrict__ patches,
                                                  float4* __restrict__ out, int B) {
    int t0 = blockIdx.x * 512 + threadIdx.x;
    int t1 = t0 + 128, t2 = t0 + 256, t3 = t0 + 384;
    bool v0 = t0 < B, v1 = t1 < B, v2 = t2 < B, v3 = t3 < B;

    PatchW P0, P1, P2, P3;
    if (v0) make_weights(patches[t0], P0);
    if (v1) make_weights(patches[t1], P1);
    if (v2) make_weights(patches[t2], P2);
    if (v3) make_weights(patches[t3], P3);

    u64 a0x, a0y, a1x, a1y, a2x, a2y, a3x, a3y;
#pragma unroll
    for (int p = 0; p < 9; p++) {
        ulonglong2 k0 = c_coef[p * 9];
        u64 s0x = k0.x, s0y = k0.y;
        u64 s1x = k0.x, s1y = k0.y;
        u64 s2x = k0.x, s2y = k0.y;
        u64 s3x = k0.x, s3y = k0.y;
#pragma unroll
        for (int q = 1; q < 9; q++) {
            ulonglong2 kq = c_coef[p * 9 + q];
            s0x = ffma2(P0.qwd[q], kq.x, s0x);
            s0y = ffma2(P0.qwd[q], kq.y, s0y);
            s1x = ffma2(P1.qwd[q], kq.x, s1x);
            s1y = ffma2(P1.qwd[q], kq.y, s1y);
            s2x = ffma2(P2.qwd[q], kq.x, s2x);
            s2y = ffma2(P2.qwd[q], kq.y, s2y);
            s3x = ffma2(P3.qwd[q], kq.x, s3x);
            s3y = ffma2(P3.qwd[q], kq.y, s3y);
        }
        if (p == 0) {
            a0x = s0x; a0y = s0y;
            a1x = s1x; a1y = s1y;
            a2x = s2x; a2y = s2y;
            a3x = s3x; a3y = s3y;
        } else {
            u64 w0 = dup2(P0.pws[p]);
            u64 w1 = dup2(P1.pws[p]);
            u64 w2 = dup2(P2.pws[p]);
            u64 w3 = dup2(P3.pws[p]);
            a0x = ffma2(w0, s0x, a0x);
            a0y = ffma2(w0, s0y, a0y);
            a1x = ffma2(w1, s1x, a1x);
            a1y = ffma2(w1, s1y, a1y);
            a2x = ffma2(w2, s2x, a2x);
            a2y = ffma2(w2, s2y, a2y);
            a3x = ffma2(w3, s3x, a3x);
            a3y = ffma2(w3, s3y, a3y);
        }
    }

    float f0, f1, f2, f3;
    if (v0) {
        unpack2(a0x, f0, f1); unpack2(a0y, f2, f3);
        out[t0] = make_float4(f0, f1, f2, f3);
    }
    if (v1) {
        unpack2(a1x, f0, f1); unpack2(a1y, f2, f3);
        out[t1] = make_float4(f0, f1, f2, f3);
    }
    if (v2) {
        unpack2(a2x, f0, f1); unpack2(a2y, f2, f3);
        out[t2] = make_float4(f0, f1, f2, f3);
    }
    if (v3) {
        unpack2(a3x, f0, f1); unpack2(a3y, f2, f3);
        out[t3] = make_float4(f0, f1, f2, f3);
    }
}

// ---------------------------------------------------------------------------
extern "C" void kernel_launch(void* const* d_in, const int* in_sizes, int n_in,
                              void* d_out, int out_size) {
    const float* patches = (const float*)d_in[0];
    int B = in_sizes[0] / 4;

    build_coef_kernel<<<1, 384>>>(
        (const float*)d_in[1], (const float*)d_in[2], (const float*)d_in[3],
        (const float*)d_in[4], (const float*)d_in[5], (const float*)d_in[6],
        (const float*)d_in[7], (const float*)d_in[8], (const float*)d_in[9],
        (const float*)d_in[10], (const float*)d_in[11], (const float*)d_in[12],
        (const float*)d_in[13], (const float*)d_in[14]);

    // Copy coefficients global -> constant via the driver path (the ONLY
    // visibility-safe route into the constant bank; async D2D, graph-legal).
    void* gaddr = nullptr;
    cudaGetSymbolAddress(&gaddr, g_coef);
    cudaMemcpyToSymbolAsync(c_coef, gaddr, 324 * sizeof(float), 0,
                            cudaMemcpyDeviceToDevice, 0);

    int blocks = (B + 511) / 512;
    quanv_main<<<blocks, 128>>>((const float4*)patches, (float4*)d_out, B);
}

// round 15
// speedup vs baseline: 1.5282x; 1.5282x over previous
#include <cuda_runtime.h>
#include <cstdint>

typedef unsigned long long u64;

// ---------------------------------------------------------------------------
// f32x2 packed helpers (Blackwell sm_103a)
// ---------------------------------------------------------------------------
__device__ __forceinline__ u64 pack2(float a, float b) {
    u64 r;
    asm("mov.b64 %0, {%1,%2};" : "=l"(r) : "f"(a), "f"(b));
    return r;
}
__device__ __forceinline__ u64 dup2(float a) { return pack2(a, a); }
__device__ __forceinline__ u64 ffma2(u64 a, u64 b, u64 c) {
    u64 d;
    asm("fma.rn.f32x2 %0, %1, %2, %3;" : "=l"(d) : "l"(a), "l"(b), "l"(c));
    return d;
}
__device__ __forceinline__ u64 fmul2(u64 a, u64 b) {
    u64 d;
    asm("mul.rn.f32x2 %0, %1, %2;" : "=l"(d) : "l"(a), "l"(b));
    return d;
}
__device__ __forceinline__ void unpack2(u64 v, float& lo, float& hi) {
    asm("mov.b64 {%0,%1}, %2;" : "=f"(lo), "=f"(hi) : "l"(v));
}

// ---------------------------------------------------------------------------
// Coefficient table: index p*9+q (p = t0*3+t1, q = t2*3+t3); each entry is
// a float4 over the 4 outputs (two packed f32x2 halves).
// Setup kernel writes g_coef (global); host-side cudaMemcpyToSymbolAsync
// moves it into c_coef (the only visibility-safe route into the constant
// bank — device-side stores are ignored by the immutable constant cache).
// ---------------------------------------------------------------------------
__device__ __align__(16) float g_coef[324];
__constant__ __align__(16) ulonglong2 c_coef[81];

__device__ __forceinline__ float2 cmulf(float2 a, float2 b) {
    return make_float2(a.x * b.x - a.y * b.y, a.x * b.y + a.y * b.x);
}
__device__ __forceinline__ float2 caddf(float2 a, float2 b) {
    return make_float2(a.x + b.x, a.y + b.y);
}

// ---------------------------------------------------------------------------
// Setup kernel (1 block, 384 threads), fully parallel.
// ---------------------------------------------------------------------------
__global__ void build_coef_kernel(
    const float* w0, const float* w1, const float* w2, const float* w3,
    const float* w4, const float* w5, const float* w6, const float* w7,
    const float* w8, const float* w9, const float* w10, const float* w11,
    const float* w12, const float* w13) {
    __shared__ float2 gm[14][4];        // 2x2 gate matrices
    __shared__ float2 su4m[2][16];      // two 4x4 SU4 matrices, row-major
    __shared__ float2 Ubuf[2][16][16];  // [buf][row k][col c]
    __shared__ float2 Ut[16][18];       // transposed Ut[c][k]; 144B rows keep
                                        // 16B alignment for LDS.128
    __shared__ float Gsh[4][16][16];    // G[i][r][c]
    const float* W[14] = {w0, w1, w2, w3, w4, w5, w6, w7, w8, w9, w10, w11, w12, w13};

    int tid = threadIdx.x;

    // ---- Stage 1: gate matrices ------------------------------------------
    if (tid < 14) {
        int j = tid % 7;
        const float* w = W[tid];
        float2 m00, m01, m10, m11;
        if (j == 0 || j == 1 || j == 5 || j == 6) {  // U3
            float th = w[0], ph = w[1], lm = w[2];
            float st, ct, sph, cph, sl, cl;
            __sincosf(0.5f * th, &st, &ct);
            __sincosf(ph, &sph, &cph);
            __sincosf(lm, &sl, &cl);
            m00 = make_float2(ct, 0.f);
            m01 = make_float2(-cl * st, -sl * st);
            m10 = make_float2(cph * st, sph * st);
            float cpl = cph * cl - sph * sl;
            float spl = sph * cl + cph * sl;
            m11 = make_float2(cpl * ct, spl * ct);
        } else if (j == 2 || j == 4) {  // RY
            float s, c;
            __sincosf(0.5f * w[0], &s, &c);
            m00 = make_float2(c, 0.f); m01 = make_float2(-s, 0.f);
            m10 = make_float2(s, 0.f); m11 = make_float2(c, 0.f);
        } else {  // RZ
            float s, c;
            __sincosf(0.5f * w[0], &s, &c);
            m00 = make_float2(c, -s); m01 = make_float2(0.f, 0.f);
            m10 = make_float2(0.f, 0.f); m11 = make_float2(c, s);
        }
        gm[tid][0] = m00; gm[tid][1] = m01; gm[tid][2] = m10; gm[tid][3] = m11;
    }
    __syncthreads();

    // ---- Stage 2: two 4x4 SU4 matrices (a = high bit, b = low bit) -------
    if (tid < 8) {
        int L = tid >> 2, c = tid & 3;
        float2 v[4];
#pragma unroll
        for (int i = 0; i < 4; i++) v[i] = make_float2(i == c ? 1.f : 0.f, 0.f);

        auto ap = [&](int gi, int m) {
            float2 g00 = gm[L * 7 + gi][0], g01 = gm[L * 7 + gi][1];
            float2 g10 = gm[L * 7 + gi][2], g11 = gm[L * 7 + gi][3];
#pragma unroll
            for (int idx = 0; idx < 4; idx++) {
                if (!(idx & m)) {
                    float2 lo = v[idx], hi = v[idx | m];
                    v[idx]     = caddf(cmulf(g00, lo), cmulf(g01, hi));
                    v[idx | m] = caddf(cmulf(g10, lo), cmulf(g11, hi));
                }
            }
        };
        auto swp = [&](int i, int j) { float2 t = v[i]; v[i] = v[j]; v[j] = t; };

        ap(0, 2);   // U3 a
        ap(1, 1);   // U3 b
        swp(2, 3);  // CNOT a->b
        ap(2, 2);   // RY a
        ap(3, 1);   // RZ b
        swp(1, 3);  // CNOT b->a
        ap(4, 2);   // RY a
        swp(2, 3);  // CNOT a->b
        ap(5, 2);   // U3 a
        ap(6, 1);   // U3 b
#pragma unroll
        for (int r = 0; r < 4; r++) su4m[L][r * 4 + c] = v[r];
    }

    // ---- Stage 3: build 16x16 unitary -----------------------------------
    if (tid < 256) {
        int k = tid >> 4, c = tid & 15;
        Ubuf[0][k][c] = make_float2(k == c ? 1.f : 0.f, 0.f);
    }

    const int gL[8]  = {0, 0, 0, 0, 1, 1, 1, 1};
    const int gwa[8] = {0, 1, 2, 3, 0, 1, 2, 3};
    const int gwb[8] = {1, 2, 3, 0, 1, 2, 3, 0};
    int cur = 0;
#pragma unroll
    for (int g = 0; g < 8; g++) {
        __syncthreads();
        if (tid < 256) {
            int k = tid >> 4, c = tid & 15;
            int ma = 1 << (3 - gwa[g]);
            int mb = 1 << (3 - gwb[g]);
            int i2 = ((k & ma) ? 2 : 0) | ((k & mb) ? 1 : 0);
            int base = k & ~(ma | mb);
            int L = gL[g];
            float2 acc = make_float2(0.f, 0.f);
#pragma unroll
            for (int j = 0; j < 4; j++) {
                int row = base | ((j & 2) ? ma : 0) | ((j & 1) ? mb : 0);
                acc = caddf(acc, cmulf(su4m[L][i2 * 4 + j], Ubuf[cur][row][c]));
            }
            Ubuf[cur ^ 1][k][c] = acc;
        }
        cur ^= 1;
    }
    __syncthreads();

    // ---- Stage 3.5: transpose so column access is contiguous over k -----
    if (tid < 256) {
        int k = tid >> 4, c = tid & 15;
        Ut[c][k] = Ubuf[cur][k][c];
    }
    __syncthreads();

    // ---- Stage 4a: G[i][r][c] = sum_k s_i(k) Re(conj U[k][r] U[k][c]) ---
    if (tid < 256) {
        int r = tid >> 4, c = tid & 15;
        float g[4] = {0.f, 0.f, 0.f, 0.f};
        const float4* pr = reinterpret_cast<const float4*>(&Ut[r][0]);
        const float4* pc = reinterpret_cast<const float4*>(&Ut[c][0]);
#pragma unroll
        for (int j = 0; j < 8; j++) {
            float4 ar = pr[j], ac = pc[j];
            float d0 = ar.x * ac.x + ar.y * ac.y;  // k = 2j
            float d1 = ar.z * ac.z + ar.w * ac.w;  // k = 2j+1
            int k0 = 2 * j, k1 = 2 * j + 1;
#pragma unroll
            for (int i = 0; i < 4; i++) {
                float s0 = ((k0 >> (3 - i)) & 1) ? -d0 : d0;
                float s1 = ((k1 >> (3 - i)) & 1) ? -d1 : d1;
                g[i] += s0 + s1;
            }
        }
#pragma unroll
        for (int i = 0; i < 4; i++) Gsh[i][r][c] = g[i];
    }
    __syncthreads();

    // ---- Stage 4b: coefficients -> global table --------------------------
    if (tid < 324) {
        int i = tid & 3;
        int pq = tid >> 2;  // 0..80
        int q = pq % 9, p = pq / 9;
        int t[4] = {p / 3, p % 3, q / 3, q % 3};
        int mask = 0, zmask = 0;
#pragma unroll
        for (int w = 0; w < 4; w++) {
            if (t[w] == 2) mask |= 1 << (3 - w);
            if (t[w] == 1) zmask |= 1 << (3 - w);
        }
        float acc = 0.f;
#pragma unroll
        for (int r = 0; r < 16; r++) {
            float sgn = (__popc(r & zmask) & 1) ? -1.f : 1.f;
            acc += sgn * Gsh[i][r][r ^ mask];
        }
        g_coef[(p * 9 + q) * 4 + i] = acc * 0.0625f;
    }
}

// ---------------------------------------------------------------------------
// Main kernel: 3 patches per thread, 128 threads/block, pure constant-port
// coefficient reads.  Per-warp LDC time is patch-count-independent (81
// loads), so 3 patches cuts chip LDC time to ~6.7us — under the ~10.5us
// ffma2 floor -> FMA pipe is the sole bind.  3-patch does NOT trigger the
// fma-inflation seen at 4-patch (R6 evidence: fma-busy 10.25us @96regs).
// ---------------------------------------------------------------------------
struct PatchW {
    u64 qwd[9];    // duplicated (w2 x w3) pair products, index 1..8 used
    float pws[9];  // (w0 x w1) pair products, index 1..8 used
};

__device__ __forceinline__ void make_weights(float4 xv, PatchW& P) {
    float xs[4] = {xv.x, xv.y, xv.z, xv.w};
    float us[4];
#pragma unroll
    for (int w = 0; w < 4; w++) {
        float e = __expf(-xs[w]);
        us[w] = __fdividef(1.0f, 1.0f + e) - 0.5f;  // u in (-0.5, 0.5)
    }
    // packed polynomials: lanes = (wire0,wire1) and (wire2,wire3)
    u64 u01 = pack2(us[0], us[1]);
    u64 u23 = pack2(us[2], us[3]);
    float cw[4], sw[4];
#pragma unroll
    for (int h = 0; h < 2; h++) {
        u64 uu = h ? u23 : u01;
        u64 z = fmul2(uu, uu);
        // sin(pi*u) deg-9 / cos(pi*u) deg-8 (abs err < 3e-5 on [-0.5,0.5])
        u64 sp = ffma2(z, dup2(0.0821458866111282f), dup2(-0.599264529320792f));
        sp = ffma2(z, sp, dup2(2.55016403987735f));
        sp = ffma2(z, sp, dup2(-5.16771278004997f));
        sp = ffma2(z, sp, dup2(3.14159265358979f));
        sp = fmul2(sp, uu);
        u64 cp = ffma2(z, dup2(0.235330630358514f), dup2(-1.33526276885459f));
        cp = ffma2(z, cp, dup2(4.05871212641677f));
        cp = ffma2(z, cp, dup2(-4.93480220054468f));
        cp = ffma2(z, cp, dup2(1.0f));
        float a, b;
        unpack2(sp, a, b);
        cw[2 * h] = -a; cw[2 * h + 1] = -b;  // cos a = -sin(pi*u)
        unpack2(cp, a, b);
        sw[2 * h] = a; sw[2 * h + 1] = b;    // sin a =  cos(pi*u)
    }
    P.qwd[1] = dup2(cw[3]);
    P.qwd[2] = dup2(sw[3]);
    P.qwd[3] = dup2(cw[2]);
    P.qwd[4] = dup2(cw[2] * cw[3]);
    P.qwd[5] = dup2(cw[2] * sw[3]);
    P.qwd[6] = dup2(sw[2]);
    P.qwd[7] = dup2(sw[2] * cw[3]);
    P.qwd[8] = dup2(sw[2] * sw[3]);
    P.pws[1] = cw[1];
    P.pws[2] = sw[1];
    P.pws[3] = cw[0];
    P.pws[4] = cw[0] * cw[1];
    P.pws[5] = cw[0] * sw[1];
    P.pws[6] = sw[0];
    P.pws[7] = sw[0] * cw[1];
    P.pws[8] = sw[0] * sw[1];
}

__global__ void __launch_bounds__(128) quanv_main(const float4* __restrict__ patches,
                                                  float4* __restrict__ out, int B) {
    int t0 = blockIdx.x * 384 + threadIdx.x;
    int t1 = t0 + 128, t2 = t0 + 256;
    bool v0 = t0 < B, v1 = t1 < B, v2 = t2 < B;

    PatchW P0, P1, P2;
    if (v0) make_weights(patches[t0], P0);
    if (v1) make_weights(patches[t1], P1);
    if (v2) make_weights(patches[t2], P2);

    u64 a0x, a0y, a1x, a1y, a2x, a2y;
#pragma unroll
    for (int p = 0; p < 9; p++) {
        ulonglong2 k0 = c_coef[p * 9];
        u64 s0x = k0.x, s0y = k0.y;
        u64 s1x = k0.x, s1y = k0.y;
        u64 s2x = k0.x, s2y = k0.y;
#pragma unroll
        for (int q = 1; q < 9; q++) {
            ulonglong2 kq = c_coef[p * 9 + q];
            s0x = ffma2(P0.qwd[q], kq.x, s0x);
            s0y = ffma2(P0.qwd[q], kq.y, s0y);
            s1x = ffma2(P1.qwd[q], kq.x, s1x);
            s1y = ffma2(P1.qwd[q], kq.y, s1y);
            s2x = ffma2(P2.qwd[q], kq.x, s2x);
            s2y = ffma2(P2.qwd[q], kq.y, s2y);
        }
        if (p == 0) {
            a0x = s0x; a0y = s0y;
            a1x = s1x; a1y = s1y;
            a2x = s2x; a2y = s2y;
        } else {
            u64 w0 = dup2(P0.pws[p]);
            u64 w1 = dup2(P1.pws[p]);
            u64 w2 = dup2(P2.pws[p]);
            a0x = ffma2(w0, s0x, a0x);
            a0y = ffma2(w0, s0y, a0y);
            a1x = ffma2(w1, s1x, a1x);
            a1y = ffma2(w1, s1y, a1y);
            a2x = ffma2(w2, s2x, a2x);
            a2y = ffma2(w2, s2y, a2y);
        }
    }

    float f0, f1, f2, f3;
    if (v0) {
        unpack2(a0x, f0, f1); unpack2(a0y, f2, f3);
        out[t0] = make_float4(f0, f1, f2, f3);
    }
    if (v1) {
        unpack2(a1x, f0, f1); unpack2(a1y, f2, f3);
        out[t1] = make_float4(f0, f1, f2, f3);
    }
    if (v2) {
        unpack2(a2x, f0, f1); unpack2(a2y, f2, f3);
        out[t2] = make_float4(f0, f1, f2, f3);
    }
}

// ---------------------------------------------------------------------------
extern "C" void kernel_launch(void* const* d_in, const int* in_sizes, int n_in,
                              void* d_out, int out_size) {
    const float* patches = (const float*)d_in[0];
    int B = in_sizes[0] / 4;

    build_coef_kernel<<<1, 384>>>(
        (const float*)d_in[1], (const float*)d_in[2], (const float*)d_in[3],
        (const float*)d_in[4], (const float*)d_in[5], (const float*)d_in[6],
        (const float*)d_in[7], (const float*)d_in[8], (const float*)d_in[9],
        (const float*)d_in[10], (const float*)d_in[11], (const float*)d_in[12],
        (const float*)d_in[13], (const float*)d_in[14]);

    // Copy coefficients global -> constant via the driver path (the ONLY
    // visibility-safe route into the constant bank; async D2D, graph-legal).
    void* gaddr = nullptr;
    cudaGetSymbolAddress(&gaddr, g_coef);
    cudaMemcpyToSymbolAsync(c_coef, gaddr, 324 * sizeof(float), 0,
                            cudaMemcpyDeviceToDevice, 0);

    int blocks = (B + 383) / 384;
    quanv_main<<<blocks, 128>>>((const float4*)patches, (float4*)d_out, B);
}